// round 5
// baseline (speedup 1.0000x reference)
#include <cuda_runtime.h>
#include <math.h>

#define NN 2048
#define CC 384
#define HH 16
#define DD 24
#define L2E 1.44269504088896340736f
#define WSZ (CC*CC)

// Scratch (allocation-free rule: __device__ globals)
__device__ unsigned g_xnh[NN*CC], g_xnl[NN*CC];      // tf32 hi/lo of layernormed x
__device__ unsigned g_wh[5*WSZ], g_wl[5*WSZ];        // tf32 hi/lo of wq,wk,wv,wg,wo
__device__ float    g_q[NN*CC];                      // [H][N][D], * D^-0.5 * log2e
__device__ float    g_kT[CC*NN];                     // [H*D][N]  (transposed!)
__device__ float    g_v[NN*CC];                      // [H][N][D]
__device__ float    g_gate[NN*CC];                   // sigmoid(xn@wg.T), [N][C]
__device__ unsigned g_gatedh[NN*CC], g_gatedl[NN*CC];// tf32 hi/lo of wa*gate
__device__ float    g_biask[NN];                     // 1e9*(mask-1)*log2e

// ---------------------------------------------------------------------------
__device__ __forceinline__ unsigned cvt_tf32(float x){
  unsigned r; asm("cvt.rna.tf32.f32 %0, %1;" : "=r"(r) : "f"(x)); return r;
}
__device__ __forceinline__ void mma_tf32(float c[4], const unsigned a[4],
                                         unsigned b0, unsigned b1){
  asm volatile("mma.sync.aligned.m16n8k8.row.col.f32.tf32.tf32.f32 "
    "{%0,%1,%2,%3}, {%4,%5,%6,%7}, {%8,%9}, {%0,%1,%2,%3};"
    : "+f"(c[0]),"+f"(c[1]),"+f"(c[2]),"+f"(c[3])
    : "r"(a[0]),"r"(a[1]),"r"(a[2]),"r"(a[3]), "r"(b0),"r"(b1));
}
__device__ __forceinline__ void cp16(void* dst, const void* src){
  unsigned d = (unsigned)__cvta_generic_to_shared(dst);
  asm volatile("cp.async.cg.shared.global [%0], [%1], 16;\n" :: "r"(d), "l"(src));
}
__device__ __forceinline__ void cp_commit(){ asm volatile("cp.async.commit_group;\n"::); }
__device__ __forceinline__ void cp_wait0(){ asm volatile("cp.async.wait_group 0;\n"::); }

// ---------------------------------------------------------------------------
// LayerNorm -> tf32 hi/lo; also key bias (log2 domain).
// ---------------------------------------------------------------------------
__global__ __launch_bounds__(128) void ln_kernel(
    const float* __restrict__ x, const float* __restrict__ mask,
    const float* __restrict__ ln_w, const float* __restrict__ ln_b) {
  int row = blockIdx.x, tid = threadIdx.x;
  const float* xr = x + row*CC;
  float v[3]; float s = 0.f;
  #pragma unroll
  for (int i=0;i<3;i++){ v[i]=xr[tid+128*i]; s+=v[i]; }
  __shared__ float red[4];
  #pragma unroll
  for (int o=16;o;o>>=1) s += __shfl_xor_sync(~0u,s,o);
  if ((tid&31)==0) red[tid>>5]=s;
  __syncthreads();
  float mu = (red[0]+red[1]+red[2]+red[3])*(1.f/CC);
  __syncthreads();
  float sq=0.f;
  #pragma unroll
  for (int i=0;i<3;i++){ float d=v[i]-mu; sq+=d*d; }
  #pragma unroll
  for (int o=16;o;o>>=1) sq += __shfl_xor_sync(~0u,sq,o);
  if ((tid&31)==0) red[tid>>5]=sq;
  __syncthreads();
  float var = (red[0]+red[1]+red[2]+red[3])*(1.f/CC);
  float rs = rsqrtf(var + 1e-5f);
  #pragma unroll
  for (int i=0;i<3;i++){
    int c = tid+128*i;
    float y = (v[i]-mu)*rs*ln_w[c] + ln_b[c];
    unsigned h = cvt_tf32(y);
    g_xnh[row*CC+c] = h;
    g_xnl[row*CC+c] = cvt_tf32(y - __uint_as_float(h));
  }
  if (tid==0) g_biask[row] = 1e9f*(mask[row]-1.f)*L2E;
}

// ---------------------------------------------------------------------------
// Split the 5 weight matrices into tf32 hi/lo (order: q,k,v,g,o).
// ---------------------------------------------------------------------------
__global__ __launch_bounds__(256) void wconv_kernel(
    const float* __restrict__ wq, const float* __restrict__ wk,
    const float* __restrict__ wv, const float* __restrict__ wg,
    const float* __restrict__ wo) {
  int which = blockIdx.y;
  const float* w = (which==0)?wq:(which==1)?wk:(which==2)?wv:(which==3)?wg:wo;
  int i = blockIdx.x*256 + threadIdx.x;
  float v = w[i];
  unsigned h = cvt_tf32(v);
  g_wh[which*WSZ + i] = h;
  g_wl[which*WSZ + i] = cvt_tf32(v - __uint_as_float(h));
}

// ---------------------------------------------------------------------------
// 3xTF32 tensor-core GEMM, 64x64 tile, K=384, cp.async double-buffered.
// Inputs pre-split into hi/lo.  D = Ah*Bh + Al*Bh + Ah*Bl.
// smem (dynamic, 73728B): buf b at b*9216 words: Ah,Al,Bh,Bl each 64*36.
// ---------------------------------------------------------------------------
__device__ __forceinline__ void gemm_tc(const unsigned* __restrict__ pAh,
                                        const unsigned* __restrict__ pAl,
                                        const unsigned* __restrict__ pBh,
                                        const unsigned* __restrict__ pBl,
                                        int n0, int c0, float acc[4][4],
                                        unsigned* sm) {
  int tid = threadIdx.x;
  int lane = tid&31, w = tid>>5;
  int wm = w>>1, wn = w&1;
  int g = lane>>2, tg = lane&3;
  int r0 = wm*16 + g, r1 = r0 + 8;

  auto stage = [&](int kt, int b){
    int k0 = kt*32;
    unsigned* base = sm + b*9216;
    #pragma unroll
    for (int i=0;i<8;i++){
      int f = tid + i*256;                 // 0..2047 16B chunks
      int a = f>>9, rr = (f&511)>>3, c4 = (f&7)*4;
      const unsigned* src =
        (a==0) ? &pAh[(n0+rr)*CC + k0 + c4] :
        (a==1) ? &pAl[(n0+rr)*CC + k0 + c4] :
        (a==2) ? &pBh[(c0+rr)*CC + k0 + c4] :
                 &pBl[(c0+rr)*CC + k0 + c4];
      cp16(base + a*2304 + rr*36 + c4, src);
    }
    cp_commit();
  };

  stage(0, 0);
  for (int kt=0; kt<12; kt++){
    int b = kt&1;
    cp_wait0();
    __syncthreads();
    if (kt < 11) stage(kt+1, b^1);
    const unsigned* Ah = sm + b*9216;
    const unsigned* Al = Ah + 2304;
    const unsigned* Bh = Al + 2304;
    const unsigned* Bl = Bh + 2304;
    #pragma unroll
    for (int ks=0; ks<4; ks++){
      int k = ks*8;
      unsigned ah[4], al[4];
      ah[0]=Ah[r0*36+k+tg]; ah[1]=Ah[r1*36+k+tg];
      ah[2]=Ah[r0*36+k+tg+4]; ah[3]=Ah[r1*36+k+tg+4];
      al[0]=Al[r0*36+k+tg]; al[1]=Al[r1*36+k+tg];
      al[2]=Al[r0*36+k+tg+4]; al[3]=Al[r1*36+k+tg+4];
      #pragma unroll
      for (int nn=0; nn<4; nn++){
        int col = wn*32 + 8*nn + g;
        unsigned bh0=Bh[col*36+k+tg], bh1=Bh[col*36+k+tg+4];
        unsigned bl0=Bl[col*36+k+tg], bl1=Bl[col*36+k+tg+4];
        mma_tf32(acc[nn], ah, bh0, bh1);
        mma_tf32(acc[nn], al, bh0, bh1);
        mma_tf32(acc[nn], ah, bl0, bl1);
      }
    }
  }
}

// ---------------------------------------------------------------------------
// All four projections (blockIdx.z selects q/k/v/g).  k stored transposed.
// ---------------------------------------------------------------------------
__device__ __forceinline__ void proj_store(int proj, int row, int col, float val,
                                           const float* __restrict__ bq){
  if (proj==0){
    val = (val + bq[col]) * (0.2041241452f * L2E);   // D^-0.5 * log2e
    g_q[(col/DD)*NN*DD + row*DD + (col%DD)] = val;
  } else if (proj==1){
    g_kT[(size_t)col*NN + row] = val;                // [H*D][N]
  } else if (proj==2){
    g_v[(col/DD)*NN*DD + row*DD + (col%DD)] = val;
  } else {
    g_gate[row*CC+col] = 1.f/(1.f+__expf(-val));
  }
}

__global__ __launch_bounds__(256) void proj_kernel(const float* __restrict__ bq) {
  extern __shared__ unsigned smu[];
  int proj = blockIdx.z;
  int c0 = blockIdx.x*64, n0 = blockIdx.y*64;
  float acc[4][4] = {};
  gemm_tc(g_xnh, g_xnl, g_wh + proj*WSZ, g_wl + proj*WSZ, n0, c0, acc, smu);
  int lane = threadIdx.x&31, w = threadIdx.x>>5;
  int wm = w>>1, wn = w&1;
  int g = lane>>2, tg = lane&3;
  int row0 = n0 + wm*16 + g, row1 = row0 + 8;
  #pragma unroll
  for (int nn=0;nn<4;nn++){
    int col = c0 + wn*32 + 8*nn + 2*tg;
    proj_store(proj, row0, col,   acc[nn][0], bq);
    proj_store(proj, row0, col+1, acc[nn][1], bq);
    proj_store(proj, row1, col,   acc[nn][2], bq);
    proj_store(proj, row1, col+1, acc[nn][3], bq);
  }
}

// ---------------------------------------------------------------------------
// Tensor-core flash attention, cp.async double-buffered over 32 key-tiles.
// Dynamic smem (61440B), float words:
//   sP[2][64*68] @0      (pair raw, then P)
//   sK[2][24*72] @8704   (K^T rows contiguous from g_kT)
//   sV[2][64*24] @12160
//   sB[2][64]    @15232  (key bias for tile)
// ---------------------------------------------------------------------------
__global__ __launch_bounds__(128) void attn_kernel(const float* __restrict__ pair) {
  extern __shared__ float sm[];
  float* sP = sm;
  float* sK = sm + 8704;
  float* sV = sm + 12160;
  float* sB = sm + 15232;

  int h = blockIdx.y, q0 = blockIdx.x*64;
  int tid = threadIdx.x;
  int w = tid>>5, lane = tid&31;
  int g = lane>>2, tg = lane&3;
  int r0 = 16*w + g, r1 = r0 + 8;

  const float* pb  = pair + (size_t)h*NN*NN + (size_t)q0*NN;
  const float* kTb = g_kT + (size_t)h*DD*NN;
  const float* vb  = g_v  + (size_t)h*NN*DD;

  // Q A-frags in registers (tf32)
  unsigned qa[3][4];
  {
    const float* qb = &g_q[(size_t)h*NN*DD + (size_t)q0*DD];
    #pragma unroll
    for (int j=0;j<3;j++){
      qa[j][0] = cvt_tf32(qb[r0*DD + 8*j+tg]);
      qa[j][1] = cvt_tf32(qb[r1*DD + 8*j+tg]);
      qa[j][2] = cvt_tf32(qb[r0*DD + 8*j+tg+4]);
      qa[j][3] = cvt_tf32(qb[r1*DD + 8*j+tg+4]);
    }
  }
  float m0=-1e30f, m1=-1e30f, l0=0.f, l1=0.f;
  float o[3][4] = {};

  auto stage = [&](int t, int b){
    int k0 = t*64;
    for (int f=tid; f<1808; f+=128){
      if (f < 1024){                       // pair 64x64
        int r = f>>4, c4 = (f&15)<<2;
        cp16(&sP[b*4352 + r*68 + c4], &pb[(size_t)r*NN + k0 + c4]);
      } else if (f < 1408){                // K^T 24x64
        int i = f-1024; int d = i>>4, c4 = (i&15)<<2;
        cp16(&sK[b*1728 + d*72 + c4], &kTb[(size_t)d*NN + k0 + c4]);
      } else if (f < 1792){                // V 64x24
        int i = f-1408; int r = i/6, c = (i - r*6)<<2;
        cp16(&sV[b*1536 + r*24 + c], &vb[(k0+r)*DD + c]);
      } else {                             // bias 64
        int i = f-1792;
        cp16(&sB[b*64 + i*4], &g_biask[k0 + i*4]);
      }
    }
    cp_commit();
  };

  stage(0, 0);
  for (int t=0;t<32;t++){
    int b = t&1;
    cp_wait0();
    __syncthreads();
    if (t < 31) stage(t+1, b^1);

    float* bP = sP + b*4352;
    const float* bK = sK + b*1728;
    const float* bV = sV + b*1536;
    const float* bB = sB + b*64;

    // C := pair*log2e + bias (fp32 exact)
    float c[8][4];
    #pragma unroll
    for (int nn=0;nn<8;nn++){
      float2 x0 = *(const float2*)&bP[r0*68 + 8*nn+2*tg];
      float2 x1 = *(const float2*)&bP[r1*68 + 8*nn+2*tg];
      float2 bv = *(const float2*)&bB[8*nn+2*tg];
      c[nn][0] = fmaf(x0.x, L2E, bv.x);
      c[nn][1] = fmaf(x0.y, L2E, bv.y);
      c[nn][2] = fmaf(x1.x, L2E, bv.x);
      c[nn][3] = fmaf(x1.y, L2E, bv.y);
    }
    // S += Q.K^T
    #pragma unroll
    for (int j=0;j<3;j++){
      #pragma unroll
      for (int nn=0;nn<8;nn++){
        unsigned b0 = cvt_tf32(bK[(8*j+tg  )*72 + 8*nn+g]);
        unsigned b1 = cvt_tf32(bK[(8*j+tg+4)*72 + 8*nn+g]);
        mma_tf32(c[nn], qa[j], b0, b1);
      }
    }

    // online softmax (log2 domain)
    float rm0=-1e30f, rm1=-1e30f;
    #pragma unroll
    for (int nn=0;nn<8;nn++){
      rm0 = fmaxf(rm0, fmaxf(c[nn][0], c[nn][1]));
      rm1 = fmaxf(rm1, fmaxf(c[nn][2], c[nn][3]));
    }
    rm0 = fmaxf(rm0, __shfl_xor_sync(~0u,rm0,1));
    rm0 = fmaxf(rm0, __shfl_xor_sync(~0u,rm0,2));
    rm1 = fmaxf(rm1, __shfl_xor_sync(~0u,rm1,1));
    rm1 = fmaxf(rm1, __shfl_xor_sync(~0u,rm1,2));
    float mn0 = fmaxf(m0, rm0), mn1 = fmaxf(m1, rm1);
    float a0 = exp2f(m0-mn0), a1 = exp2f(m1-mn1);
    float ls0=0.f, ls1=0.f;
    #pragma unroll
    for (int nn=0;nn<8;nn++){
      float p00 = exp2f(c[nn][0]-mn0);
      float p01 = exp2f(c[nn][1]-mn0);
      float p10 = exp2f(c[nn][2]-mn1);
      float p11 = exp2f(c[nn][3]-mn1);
      ls0 += p00+p01; ls1 += p10+p11;
      *(float2*)&bP[r0*68 + 8*nn+2*tg] = make_float2(p00,p01);
      *(float2*)&bP[r1*68 + 8*nn+2*tg] = make_float2(p10,p11);
    }
    ls0 += __shfl_xor_sync(~0u,ls0,1); ls0 += __shfl_xor_sync(~0u,ls0,2);
    ls1 += __shfl_xor_sync(~0u,ls1,1); ls1 += __shfl_xor_sync(~0u,ls1,2);
    l0 = l0*a0 + ls0; l1 = l1*a1 + ls1; m0 = mn0; m1 = mn1;
    #pragma unroll
    for (int nn=0;nn<3;nn++){
      o[nn][0]*=a0; o[nn][1]*=a0; o[nn][2]*=a1; o[nn][3]*=a1;
    }
    __syncwarp();   // P rows warp-private; order STS before LDS

    // O += P.V
    #pragma unroll
    for (int j=0;j<8;j++){
      unsigned a[4];
      a[0] = cvt_tf32(bP[r0*68 + 8*j+tg]);
      a[1] = cvt_tf32(bP[r1*68 + 8*j+tg]);
      a[2] = cvt_tf32(bP[r0*68 + 8*j+tg+4]);
      a[3] = cvt_tf32(bP[r1*68 + 8*j+tg+4]);
      #pragma unroll
      for (int nn=0;nn<3;nn++){
        unsigned b0 = cvt_tf32(bV[(8*j+tg  )*24 + 8*nn+g]);
        unsigned b1 = cvt_tf32(bV[(8*j+tg+4)*24 + 8*nn+g]);
        mma_tf32(o[nn], a, b0, b1);
      }
    }
  }

  // epilogue: normalize + gate -> hi/lo for the output GEMM
  float il0 = 1.f/l0, il1 = 1.f/l1;
  int n0g = q0 + r0, n1g = q0 + r1;
  #pragma unroll
  for (int nn=0;nn<3;nn++){
    int col = h*DD + 8*nn + 2*tg;
    float2 gt0 = *(const float2*)&g_gate[n0g*CC + col];
    float2 gt1 = *(const float2*)&g_gate[n1g*CC + col];
    float y[4] = { o[nn][0]*il0*gt0.x, o[nn][1]*il0*gt0.y,
                   o[nn][2]*il1*gt1.x, o[nn][3]*il1*gt1.y };
    int idx[4] = { n0g*CC+col, n0g*CC+col+1, n1g*CC+col, n1g*CC+col+1 };
    #pragma unroll
    for (int i=0;i<4;i++){
      unsigned hx = cvt_tf32(y[i]);
      g_gatedh[idx[i]] = hx;
      g_gatedl[idx[i]] = cvt_tf32(y[i] - __uint_as_float(hx));
    }
  }
}

// ---------------------------------------------------------------------------
// Output projection: out = gated @ wo.T  (3xTF32, pipelined)
// ---------------------------------------------------------------------------
__global__ __launch_bounds__(256) void out_kernel(float* __restrict__ out) {
  extern __shared__ unsigned smu[];
  int c0 = blockIdx.x*64, n0 = blockIdx.y*64;
  float acc[4][4] = {};
  gemm_tc(g_gatedh, g_gatedl, g_wh + 4*WSZ, g_wl + 4*WSZ, n0, c0, acc, smu);
  int lane = threadIdx.x&31, w = threadIdx.x>>5;
  int wm = w>>1, wn = w&1;
  int g = lane>>2, tg = lane&3;
  int row0 = n0 + wm*16 + g, row1 = row0 + 8;
  #pragma unroll
  for (int nn=0;nn<4;nn++){
    int col = c0 + wn*32 + 8*nn + 2*tg;
    *(float2*)&out[row0*CC+col] = make_float2(acc[nn][0], acc[nn][1]);
    *(float2*)&out[row1*CC+col] = make_float2(acc[nn][2], acc[nn][3]);
  }
}

// ---------------------------------------------------------------------------
extern "C" void kernel_launch(void* const* d_in, const int* in_sizes, int n_in,
                              void* d_out, int out_size) {
  const float* x    = (const float*)d_in[0];
  const float* mask = (const float*)d_in[1];
  const float* pair = (const float*)d_in[2];
  const float* ln_w = (const float*)d_in[3];
  const float* ln_b = (const float*)d_in[4];
  const float* wq   = (const float*)d_in[5];
  const float* bq   = (const float*)d_in[6];
  const float* wk   = (const float*)d_in[7];
  const float* wv   = (const float*)d_in[8];
  const float* wg   = (const float*)d_in[9];
  const float* wo   = (const float*)d_in[10];
  float* out = (float*)d_out;

  cudaFuncSetAttribute(proj_kernel, cudaFuncAttributeMaxDynamicSharedMemorySize, 73728);
  cudaFuncSetAttribute(out_kernel,  cudaFuncAttributeMaxDynamicSharedMemorySize, 73728);
  cudaFuncSetAttribute(attn_kernel, cudaFuncAttributeMaxDynamicSharedMemorySize, 61440);

  ln_kernel<<<NN,128>>>(x,mask,ln_w,ln_b);
  wconv_kernel<<<dim3(WSZ/256,5),256>>>(wq,wk,wv,wg,wo);
  proj_kernel<<<dim3(6,32,4),256,73728>>>(bq);
  attn_kernel<<<dim3(32,16),128,61440>>>(pair);
  out_kernel<<<dim3(6,32),256,73728>>>(out);
}

// round 6
// speedup vs baseline: 1.4154x; 1.4154x over previous
#include <cuda_runtime.h>
#include <math.h>

#define NN 2048
#define CC 384
#define HH 16
#define DD 24
#define L2E 1.44269504088896340736f
#define WSZ (CC*CC)

// Scratch (allocation-free rule: __device__ globals)
__device__ unsigned g_xnh[NN*CC], g_xnl[NN*CC];      // tf32 hi/lo of layernormed x
__device__ unsigned g_wh[5*WSZ], g_wl[5*WSZ];        // tf32 hi/lo of wq,wk,wv,wg,wo
__device__ unsigned g_q[NN*CC];                      // [H][N][D], *D^-0.5*log2e, tf32
__device__ unsigned g_kT[CC*NN];                     // [H*D][N], tf32 (transposed)
__device__ unsigned g_v[NN*CC];                      // [H][N][D], tf32
__device__ float    g_gate[NN*CC];                   // sigmoid(xn@wg.T), [N][C]
__device__ unsigned g_gatedh[NN*CC], g_gatedl[NN*CC];// tf32 hi/lo of wa*gate
__device__ float    g_biask[NN];                     // 1e9*(mask-1)*log2e

// ---------------------------------------------------------------------------
__device__ __forceinline__ unsigned cvt_tf32(float x){
  unsigned r; asm("cvt.rna.tf32.f32 %0, %1;" : "=r"(r) : "f"(x)); return r;
}
__device__ __forceinline__ void mma_tf32(float c[4], const unsigned a[4],
                                         unsigned b0, unsigned b1){
  asm volatile("mma.sync.aligned.m16n8k8.row.col.f32.tf32.tf32.f32 "
    "{%0,%1,%2,%3}, {%4,%5,%6,%7}, {%8,%9}, {%0,%1,%2,%3};"
    : "+f"(c[0]),"+f"(c[1]),"+f"(c[2]),"+f"(c[3])
    : "r"(a[0]),"r"(a[1]),"r"(a[2]),"r"(a[3]), "r"(b0),"r"(b1));
}
__device__ __forceinline__ void cp16(void* dst, const void* src){
  unsigned d = (unsigned)__cvta_generic_to_shared(dst);
  asm volatile("cp.async.cg.shared.global [%0], [%1], 16;\n" :: "r"(d), "l"(src));
}
__device__ __forceinline__ void cp_commit(){ asm volatile("cp.async.commit_group;\n"::); }
__device__ __forceinline__ void cp_wait0(){ asm volatile("cp.async.wait_group 0;\n"::); }

// ---------------------------------------------------------------------------
// LayerNorm -> tf32 hi/lo; also key bias (log2 domain).
// ---------------------------------------------------------------------------
__global__ __launch_bounds__(128) void ln_kernel(
    const float* __restrict__ x, const float* __restrict__ mask,
    const float* __restrict__ ln_w, const float* __restrict__ ln_b) {
  int row = blockIdx.x, tid = threadIdx.x;
  const float* xr = x + row*CC;
  float v[3]; float s = 0.f;
  #pragma unroll
  for (int i=0;i<3;i++){ v[i]=xr[tid+128*i]; s+=v[i]; }
  __shared__ float red[4];
  #pragma unroll
  for (int o=16;o;o>>=1) s += __shfl_xor_sync(~0u,s,o);
  if ((tid&31)==0) red[tid>>5]=s;
  __syncthreads();
  float mu = (red[0]+red[1]+red[2]+red[3])*(1.f/CC);
  __syncthreads();
  float sq=0.f;
  #pragma unroll
  for (int i=0;i<3;i++){ float d=v[i]-mu; sq+=d*d; }
  #pragma unroll
  for (int o=16;o;o>>=1) sq += __shfl_xor_sync(~0u,sq,o);
  if ((tid&31)==0) red[tid>>5]=sq;
  __syncthreads();
  float var = (red[0]+red[1]+red[2]+red[3])*(1.f/CC);
  float rs = rsqrtf(var + 1e-5f);
  #pragma unroll
  for (int i=0;i<3;i++){
    int c = tid+128*i;
    float y = (v[i]-mu)*rs*ln_w[c] + ln_b[c];
    unsigned h = cvt_tf32(y);
    g_xnh[row*CC+c] = h;
    g_xnl[row*CC+c] = cvt_tf32(y - __uint_as_float(h));
  }
  if (tid==0) g_biask[row] = 1e9f*(mask[row]-1.f)*L2E;
}

// ---------------------------------------------------------------------------
// Split the 5 weight matrices into tf32 hi/lo (order: q,k,v,g,o).
// ---------------------------------------------------------------------------
__global__ __launch_bounds__(256) void wconv_kernel(
    const float* __restrict__ wq, const float* __restrict__ wk,
    const float* __restrict__ wv, const float* __restrict__ wg,
    const float* __restrict__ wo) {
  int which = blockIdx.y;
  const float* w = (which==0)?wq:(which==1)?wk:(which==2)?wv:(which==3)?wg:wo;
  int i = blockIdx.x*256 + threadIdx.x;
  float v = w[i];
  unsigned h = cvt_tf32(v);
  g_wh[which*WSZ + i] = h;
  g_wl[which*WSZ + i] = cvt_tf32(v - __uint_as_float(h));
}

// ---------------------------------------------------------------------------
// 3xTF32 tensor-core GEMM, 64x64 tile, K=384, cp.async double-buffered.
// ---------------------------------------------------------------------------
__device__ __forceinline__ void gemm_tc(const unsigned* __restrict__ pAh,
                                        const unsigned* __restrict__ pAl,
                                        const unsigned* __restrict__ pBh,
                                        const unsigned* __restrict__ pBl,
                                        int n0, int c0, float acc[4][4],
                                        unsigned* sm) {
  int tid = threadIdx.x;
  int lane = tid&31, w = tid>>5;
  int wm = w>>1, wn = w&1;
  int g = lane>>2, tg = lane&3;
  int r0 = wm*16 + g, r1 = r0 + 8;

  auto stage = [&](int kt, int b){
    int k0 = kt*32;
    unsigned* base = sm + b*9216;
    #pragma unroll
    for (int i=0;i<8;i++){
      int f = tid + i*256;                 // 0..2047 16B chunks
      int a = f>>9, rr = (f&511)>>3, c4 = (f&7)*4;
      const unsigned* src =
        (a==0) ? &pAh[(n0+rr)*CC + k0 + c4] :
        (a==1) ? &pAl[(n0+rr)*CC + k0 + c4] :
        (a==2) ? &pBh[(c0+rr)*CC + k0 + c4] :
                 &pBl[(c0+rr)*CC + k0 + c4];
      cp16(base + a*2304 + rr*36 + c4, src);
    }
    cp_commit();
  };

  stage(0, 0);
  for (int kt=0; kt<12; kt++){
    int b = kt&1;
    cp_wait0();
    __syncthreads();
    if (kt < 11) stage(kt+1, b^1);
    const unsigned* Ah = sm + b*9216;
    const unsigned* Al = Ah + 2304;
    const unsigned* Bh = Al + 2304;
    const unsigned* Bl = Bh + 2304;
    #pragma unroll
    for (int ks=0; ks<4; ks++){
      int k = ks*8;
      unsigned ah[4], al[4];
      ah[0]=Ah[r0*36+k+tg]; ah[1]=Ah[r1*36+k+tg];
      ah[2]=Ah[r0*36+k+tg+4]; ah[3]=Ah[r1*36+k+tg+4];
      al[0]=Al[r0*36+k+tg]; al[1]=Al[r1*36+k+tg];
      al[2]=Al[r0*36+k+tg+4]; al[3]=Al[r1*36+k+tg+4];
      #pragma unroll
      for (int nn=0; nn<4; nn++){
        int col = wn*32 + 8*nn + g;
        unsigned bh0=Bh[col*36+k+tg], bh1=Bh[col*36+k+tg+4];
        unsigned bl0=Bl[col*36+k+tg], bl1=Bl[col*36+k+tg+4];
        mma_tf32(acc[nn], ah, bh0, bh1);
        mma_tf32(acc[nn], al, bh0, bh1);
        mma_tf32(acc[nn], ah, bl0, bl1);
      }
    }
  }
}

// ---------------------------------------------------------------------------
// All four projections (blockIdx.z selects q/k/v/g).
// q/k/v stored pre-converted to tf32; k transposed to [H*D][N].
// ---------------------------------------------------------------------------
__device__ __forceinline__ void proj_store(int proj, int row, int col, float val,
                                           const float* __restrict__ bq){
  if (proj==0){
    val = (val + bq[col]) * (0.2041241452f * L2E);   // D^-0.5 * log2e
    g_q[(col/DD)*NN*DD + row*DD + (col%DD)] = cvt_tf32(val);
  } else if (proj==1){
    g_kT[(size_t)col*NN + row] = cvt_tf32(val);      // [H*D][N]
  } else if (proj==2){
    g_v[(col/DD)*NN*DD + row*DD + (col%DD)] = cvt_tf32(val);
  } else {
    g_gate[row*CC+col] = 1.f/(1.f+__expf(-val));
  }
}

__global__ __launch_bounds__(256) void proj_kernel(const float* __restrict__ bq) {
  extern __shared__ unsigned smu[];
  int proj = blockIdx.z;
  int c0 = blockIdx.x*64, n0 = blockIdx.y*64;
  float acc[4][4] = {};
  gemm_tc(g_xnh, g_xnl, g_wh + proj*WSZ, g_wl + proj*WSZ, n0, c0, acc, smu);
  int lane = threadIdx.x&31, w = threadIdx.x>>5;
  int wm = w>>1, wn = w&1;
  int g = lane>>2, tg = lane&3;
  int row0 = n0 + wm*16 + g, row1 = row0 + 8;
  #pragma unroll
  for (int nn=0;nn<4;nn++){
    int col = c0 + wn*32 + 8*nn + 2*tg;
    proj_store(proj, row0, col,   acc[nn][0], bq);
    proj_store(proj, row0, col+1, acc[nn][1], bq);
    proj_store(proj, row1, col,   acc[nn][2], bq);
    proj_store(proj, row1, col+1, acc[nn][3], bq);
  }
}

// ---------------------------------------------------------------------------
// Tensor-core flash attention, 32-key tiles, cp.async double-buffered.
// Dynamic smem (32256B), float words:
//   sPair[2][64*36] @0     (pair tile; overwritten in place by P)
//   sK  [2][24*40]  @4608  (K^T tf32, stride 40 -> B-frag banks 8tg+g, CF)
//   sV  [2][32*24]  @6528  (V tf32, banks 24tg+g, CF)
// Staging slots fixed per thread; sources advance by constant stride per tile.
// ---------------------------------------------------------------------------
__global__ __launch_bounds__(128) void attn_kernel(const float* __restrict__ pair) {
  extern __shared__ float sm[];
  float* sPair   = sm;                       // 2 x 2304
  unsigned* sK   = (unsigned*)(sm + 4608);   // 2 x 960
  unsigned* sV   = (unsigned*)(sm + 6528);   // 2 x 768

  int h = blockIdx.y, q0 = blockIdx.x*64;
  int tid = threadIdx.x;
  int w = tid>>5, lane = tid&31;
  int g = lane>>2, tg = lane&3;
  int r0 = 16*w + g, r1 = r0 + 8;

  const float* pb     = pair + (size_t)h*NN*NN + (size_t)q0*NN;
  const unsigned* kTb = g_kT + (size_t)h*DD*NN;
  const unsigned* vb  = g_v  + (size_t)h*NN*DD;

  // ---- fixed staging slots (computed once) ----
  const float*    psrc[4]; int pdst[4];
  #pragma unroll
  for (int i=0;i<4;i++){
    int f = tid + 128*i;                   // 512 chunks: 64 rows x 8
    int r = f>>3, c4 = (f&7)*4;
    psrc[i] = pb + (size_t)r*NN + c4;
    pdst[i] = r*36 + c4;
  }
  const unsigned* ksrc[2]; int kdst[2];
  {
    int f = tid;                           // 192 chunks: 24 rows x 8
    ksrc[0] = kTb + (size_t)(f>>3)*NN + (f&7)*4; kdst[0] = (f>>3)*40 + (f&7)*4;
    int f2 = tid + 128;
    ksrc[1] = kTb + (size_t)(f2>>3)*NN + (f2&7)*4; kdst[1] = (f2>>3)*40 + (f2&7)*4;
  }
  const unsigned* vsrc[2]; int vdst[2];
  {
    int f = tid;                           // 192 chunks: 32 rows x 6
    int r = f/6, c = (f-6*r)*4;
    vsrc[0] = vb + r*DD + c; vdst[0] = r*24 + c;
    int f2 = tid + 128; int r2 = f2/6, c2 = (f2-6*r2)*4;
    vsrc[1] = vb + r2*DD + c2; vdst[1] = r2*24 + c2;
  }
  bool lo64 = (tid < 64);

  auto stage = [&](int t, int b){
    int koff = t*32;                       // key offset (elements)
    #pragma unroll
    for (int i=0;i<4;i++) cp16(sPair + b*2304 + pdst[i], psrc[i] + koff);
    cp16(sK + b*960 + kdst[0], ksrc[0] + koff);
    if (lo64) cp16(sK + b*960 + kdst[1], ksrc[1] + koff);
    cp16(sV + b*768 + vdst[0], vsrc[0] + koff*DD);
    if (lo64) cp16(sV + b*768 + vdst[1], vsrc[1] + koff*DD);
    cp_commit();
  };

  // Q A-frags in registers (pre-converted tf32)
  unsigned qa[3][4];
  {
    const unsigned* qb = &g_q[(size_t)h*NN*DD + (size_t)q0*DD];
    #pragma unroll
    for (int j=0;j<3;j++){
      qa[j][0] = qb[r0*DD + 8*j+tg];
      qa[j][1] = qb[r1*DD + 8*j+tg];
      qa[j][2] = qb[r0*DD + 8*j+tg+4];
      qa[j][3] = qb[r1*DD + 8*j+tg+4];
    }
  }
  float m0=-1e30f, m1=-1e30f, l0=0.f, l1=0.f;
  float o[3][4] = {};

  stage(0, 0);
  for (int t=0;t<64;t++){
    int b = t&1, k0 = t*32;
    cp_wait0();
    __syncthreads();
    if (t < 63) stage(t+1, b^1);

    float* bP = sPair + b*2304;
    const unsigned* bK = sK + b*960;
    const unsigned* bV = sV + b*768;
    const float* bb = &g_biask[k0];

    // C := pair*log2e + bias (fp32 exact); bias via L1-cached gmem loads
    float c[4][4];
    #pragma unroll
    for (int nn=0;nn<4;nn++){
      float2 x0 = *(const float2*)&bP[r0*36 + 8*nn+2*tg];
      float2 x1 = *(const float2*)&bP[r1*36 + 8*nn+2*tg];
      float2 bv = *(const float2*)&bb[8*nn+2*tg];
      c[nn][0] = fmaf(x0.x, L2E, bv.x);
      c[nn][1] = fmaf(x0.y, L2E, bv.y);
      c[nn][2] = fmaf(x1.x, L2E, bv.x);
      c[nn][3] = fmaf(x1.y, L2E, bv.y);
    }
    // S += Q.K^T  (B-frags raw, pre-converted)
    #pragma unroll
    for (int j=0;j<3;j++){
      #pragma unroll
      for (int nn=0;nn<4;nn++){
        unsigned b0 = bK[(8*j+tg  )*40 + 8*nn+g];
        unsigned b1 = bK[(8*j+tg+4)*40 + 8*nn+g];
        mma_tf32(c[nn], qa[j], b0, b1);
      }
    }

    // online softmax (log2 domain); P stored pre-converted to tf32
    float rm0=-1e30f, rm1=-1e30f;
    #pragma unroll
    for (int nn=0;nn<4;nn++){
      rm0 = fmaxf(rm0, fmaxf(c[nn][0], c[nn][1]));
      rm1 = fmaxf(rm1, fmaxf(c[nn][2], c[nn][3]));
    }
    rm0 = fmaxf(rm0, __shfl_xor_sync(~0u,rm0,1));
    rm0 = fmaxf(rm0, __shfl_xor_sync(~0u,rm0,2));
    rm1 = fmaxf(rm1, __shfl_xor_sync(~0u,rm1,1));
    rm1 = fmaxf(rm1, __shfl_xor_sync(~0u,rm1,2));
    float mn0 = fmaxf(m0, rm0), mn1 = fmaxf(m1, rm1);
    float a0 = exp2f(m0-mn0), a1 = exp2f(m1-mn1);
    float ls0=0.f, ls1=0.f;
    #pragma unroll
    for (int nn=0;nn<4;nn++){
      float p00 = exp2f(c[nn][0]-mn0);
      float p01 = exp2f(c[nn][1]-mn0);
      float p10 = exp2f(c[nn][2]-mn1);
      float p11 = exp2f(c[nn][3]-mn1);
      ls0 += p00+p01; ls1 += p10+p11;
      *(float2*)&bP[r0*36 + 8*nn+2*tg] =
        make_float2(__uint_as_float(cvt_tf32(p00)), __uint_as_float(cvt_tf32(p01)));
      *(float2*)&bP[r1*36 + 8*nn+2*tg] =
        make_float2(__uint_as_float(cvt_tf32(p10)), __uint_as_float(cvt_tf32(p11)));
    }
    ls0 += __shfl_xor_sync(~0u,ls0,1); ls0 += __shfl_xor_sync(~0u,ls0,2);
    ls1 += __shfl_xor_sync(~0u,ls1,1); ls1 += __shfl_xor_sync(~0u,ls1,2);
    l0 = l0*a0 + ls0; l1 = l1*a1 + ls1; m0 = mn0; m1 = mn1;
    #pragma unroll
    for (int nn=0;nn<3;nn++){
      o[nn][0]*=a0; o[nn][1]*=a0; o[nn][2]*=a1; o[nn][3]*=a1;
    }
    __syncwarp();   // P rows warp-private; order STS before LDS

    // O += P.V  (all frags raw tf32)
    const unsigned* bPu = (const unsigned*)bP;
    #pragma unroll
    for (int j=0;j<4;j++){
      unsigned a[4];
      a[0] = bPu[r0*36 + 8*j+tg];
      a[1] = bPu[r1*36 + 8*j+tg];
      a[2] = bPu[r0*36 + 8*j+tg+4];
      a[3] = bPu[r1*36 + 8*j+tg+4];
      #pragma unroll
      for (int nn=0;nn<3;nn++){
        unsigned b0 = bV[(8*j+tg  )*24 + 8*nn+g];
        unsigned b1 = bV[(8*j+tg+4)*24 + 8*nn+g];
        mma_tf32(o[nn], a, b0, b1);
      }
    }
  }

  // epilogue: normalize + gate -> hi/lo for the output GEMM
  float il0 = 1.f/l0, il1 = 1.f/l1;
  int n0g = q0 + r0, n1g = q0 + r1;
  #pragma unroll
  for (int nn=0;nn<3;nn++){
    int col = h*DD + 8*nn + 2*tg;
    float2 gt0 = *(const float2*)&g_gate[n0g*CC + col];
    float2 gt1 = *(const float2*)&g_gate[n1g*CC + col];
    float y[4] = { o[nn][0]*il0*gt0.x, o[nn][1]*il0*gt0.y,
                   o[nn][2]*il1*gt1.x, o[nn][3]*il1*gt1.y };
    int idx[4] = { n0g*CC+col, n0g*CC+col+1, n1g*CC+col, n1g*CC+col+1 };
    #pragma unroll
    for (int i=0;i<4;i++){
      unsigned hx = cvt_tf32(y[i]);
      g_gatedh[idx[i]] = hx;
      g_gatedl[idx[i]] = cvt_tf32(y[i] - __uint_as_float(hx));
    }
  }
}

// ---------------------------------------------------------------------------
// Output projection: out = gated @ wo.T  (3xTF32, pipelined)
// ---------------------------------------------------------------------------
__global__ __launch_bounds__(256) void out_kernel(float* __restrict__ out) {
  extern __shared__ unsigned smu[];
  int c0 = blockIdx.x*64, n0 = blockIdx.y*64;
  float acc[4][4] = {};
  gemm_tc(g_gatedh, g_gatedl, g_wh + 4*WSZ, g_wl + 4*WSZ, n0, c0, acc, smu);
  int lane = threadIdx.x&31, w = threadIdx.x>>5;
  int wm = w>>1, wn = w&1;
  int g = lane>>2, tg = lane&3;
  int row0 = n0 + wm*16 + g, row1 = row0 + 8;
  #pragma unroll
  for (int nn=0;nn<4;nn++){
    int col = c0 + wn*32 + 8*nn + 2*tg;
    *(float2*)&out[row0*CC+col] = make_float2(acc[nn][0], acc[nn][1]);
    *(float2*)&out[row1*CC+col] = make_float2(acc[nn][2], acc[nn][3]);
  }
}

// ---------------------------------------------------------------------------
extern "C" void kernel_launch(void* const* d_in, const int* in_sizes, int n_in,
                              void* d_out, int out_size) {
  const float* x    = (const float*)d_in[0];
  const float* mask = (const float*)d_in[1];
  const float* pair = (const float*)d_in[2];
  const float* ln_w = (const float*)d_in[3];
  const float* ln_b = (const float*)d_in[4];
  const float* wq   = (const float*)d_in[5];
  const float* bq   = (const float*)d_in[6];
  const float* wk   = (const float*)d_in[7];
  const float* wv   = (const float*)d_in[8];
  const float* wg   = (const float*)d_in[9];
  const float* wo   = (const float*)d_in[10];
  float* out = (float*)d_out;

  cudaFuncSetAttribute(proj_kernel, cudaFuncAttributeMaxDynamicSharedMemorySize, 73728);
  cudaFuncSetAttribute(out_kernel,  cudaFuncAttributeMaxDynamicSharedMemorySize, 73728);
  cudaFuncSetAttribute(attn_kernel, cudaFuncAttributeMaxDynamicSharedMemorySize, 32256);

  ln_kernel<<<NN,128>>>(x,mask,ln_w,ln_b);
  wconv_kernel<<<dim3(WSZ/256,5),256>>>(wq,wk,wv,wg,wo);
  proj_kernel<<<dim3(6,32,4),256,73728>>>(bq);
  attn_kernel<<<dim3(32,16),128,32256>>>(pair);
  out_kernel<<<dim3(6,32),256,73728>>>(out);
}

// round 7
// speedup vs baseline: 1.4168x; 1.0010x over previous
#include <cuda_runtime.h>
#include <math.h>

#define NN 2048
#define CC 384
#define HH 16
#define DD 24
#define L2E 1.44269504088896340736f
#define WSZ (CC*CC)

// Scratch (allocation-free rule: __device__ globals)
__device__ unsigned g_xnh[NN*CC], g_xnl[NN*CC];      // tf32 hi/lo of layernormed x
__device__ unsigned g_wh[5*WSZ], g_wl[5*WSZ];        // tf32 hi/lo of wq,wk,wv,wg,wo
__device__ unsigned g_q[NN*CC];                      // [H][N][D], *D^-0.5*log2e, tf32
__device__ unsigned g_kT[CC*NN];                     // [H*D][N], tf32 (transposed)
__device__ unsigned g_v[NN*CC];                      // [H][N][D], tf32
__device__ float    g_gate[NN*CC];                   // sigmoid(xn@wg.T), [N][C]
__device__ unsigned g_gatedh[NN*CC], g_gatedl[NN*CC];// tf32 hi/lo of wa*gate
__device__ float    g_biask[NN];                     // 1e9*(mask-1)*log2e

// ---------------------------------------------------------------------------
__device__ __forceinline__ unsigned cvt_tf32(float x){
  unsigned r; asm("cvt.rna.tf32.f32 %0, %1;" : "=r"(r) : "f"(x)); return r;
}
__device__ __forceinline__ void mma_tf32(float c[4], const unsigned a[4],
                                         unsigned b0, unsigned b1){
  asm volatile("mma.sync.aligned.m16n8k8.row.col.f32.tf32.tf32.f32 "
    "{%0,%1,%2,%3}, {%4,%5,%6,%7}, {%8,%9}, {%0,%1,%2,%3};"
    : "+f"(c[0]),"+f"(c[1]),"+f"(c[2]),"+f"(c[3])
    : "r"(a[0]),"r"(a[1]),"r"(a[2]),"r"(a[3]), "r"(b0),"r"(b1));
}
__device__ __forceinline__ void cp16(void* dst, const void* src){
  unsigned d = (unsigned)__cvta_generic_to_shared(dst);
  asm volatile("cp.async.cg.shared.global [%0], [%1], 16;\n" :: "r"(d), "l"(src));
}
__device__ __forceinline__ void cp_commit(){ asm volatile("cp.async.commit_group;\n"::); }
__device__ __forceinline__ void cp_wait0(){ asm volatile("cp.async.wait_group 0;\n"::); }

// ---------------------------------------------------------------------------
// LayerNorm -> tf32 hi/lo; also key bias (log2 domain).
// ---------------------------------------------------------------------------
__global__ __launch_bounds__(128) void ln_kernel(
    const float* __restrict__ x, const float* __restrict__ mask,
    const float* __restrict__ ln_w, const float* __restrict__ ln_b) {
  int row = blockIdx.x, tid = threadIdx.x;
  const float* xr = x + row*CC;
  float v[3]; float s = 0.f;
  #pragma unroll
  for (int i=0;i<3;i++){ v[i]=xr[tid+128*i]; s+=v[i]; }
  __shared__ float red[4];
  #pragma unroll
  for (int o=16;o;o>>=1) s += __shfl_xor_sync(~0u,s,o);
  if ((tid&31)==0) red[tid>>5]=s;
  __syncthreads();
  float mu = (red[0]+red[1]+red[2]+red[3])*(1.f/CC);
  __syncthreads();
  float sq=0.f;
  #pragma unroll
  for (int i=0;i<3;i++){ float d=v[i]-mu; sq+=d*d; }
  #pragma unroll
  for (int o=16;o;o>>=1) sq += __shfl_xor_sync(~0u,sq,o);
  if ((tid&31)==0) red[tid>>5]=sq;
  __syncthreads();
  float var = (red[0]+red[1]+red[2]+red[3])*(1.f/CC);
  float rs = rsqrtf(var + 1e-5f);
  #pragma unroll
  for (int i=0;i<3;i++){
    int c = tid+128*i;
    float y = (v[i]-mu)*rs*ln_w[c] + ln_b[c];
    unsigned h = cvt_tf32(y);
    g_xnh[row*CC+c] = h;
    g_xnl[row*CC+c] = cvt_tf32(y - __uint_as_float(h));
  }
  if (tid==0) g_biask[row] = 1e9f*(mask[row]-1.f)*L2E;
}

// ---------------------------------------------------------------------------
// Split the 5 weight matrices into tf32 hi/lo (order: q,k,v,g,o).
// ---------------------------------------------------------------------------
__global__ __launch_bounds__(256) void wconv_kernel(
    const float* __restrict__ wq, const float* __restrict__ wk,
    const float* __restrict__ wv, const float* __restrict__ wg,
    const float* __restrict__ wo) {
  int which = blockIdx.y;
  const float* w = (which==0)?wq:(which==1)?wk:(which==2)?wv:(which==3)?wg:wo;
  int i = blockIdx.x*256 + threadIdx.x;
  float v = w[i];
  unsigned h = cvt_tf32(v);
  g_wh[which*WSZ + i] = h;
  g_wl[which*WSZ + i] = cvt_tf32(v - __uint_as_float(h));
}

// ---------------------------------------------------------------------------
// 3xTF32 tensor-core GEMM, 64x64 tile, K=384, cp.async double-buffered.
// ---------------------------------------------------------------------------
__device__ __forceinline__ void gemm_tc(const unsigned* __restrict__ pAh,
                                        const unsigned* __restrict__ pAl,
                                        const unsigned* __restrict__ pBh,
                                        const unsigned* __restrict__ pBl,
                                        int n0, int c0, float acc[4][4],
                                        unsigned* sm) {
  int tid = threadIdx.x;
  int lane = tid&31, w = tid>>5;
  int wm = w>>1, wn = w&1;
  int g = lane>>2, tg = lane&3;
  int r0 = wm*16 + g, r1 = r0 + 8;

  auto stage = [&](int kt, int b){
    int k0 = kt*32;
    unsigned* base = sm + b*9216;
    #pragma unroll
    for (int i=0;i<8;i++){
      int f = tid + i*256;                 // 0..2047 16B chunks
      int a = f>>9, rr = (f&511)>>3, c4 = (f&7)*4;
      const unsigned* src =
        (a==0) ? &pAh[(n0+rr)*CC + k0 + c4] :
        (a==1) ? &pAl[(n0+rr)*CC + k0 + c4] :
        (a==2) ? &pBh[(c0+rr)*CC + k0 + c4] :
                 &pBl[(c0+rr)*CC + k0 + c4];
      cp16(base + a*2304 + rr*36 + c4, src);
    }
    cp_commit();
  };

  stage(0, 0);
  for (int kt=0; kt<12; kt++){
    int b = kt&1;
    cp_wait0();
    __syncthreads();
    if (kt < 11) stage(kt+1, b^1);
    const unsigned* Ah = sm + b*9216;
    const unsigned* Al = Ah + 2304;
    const unsigned* Bh = Al + 2304;
    const unsigned* Bl = Bh + 2304;
    #pragma unroll
    for (int ks=0; ks<4; ks++){
      int k = ks*8;
      unsigned ah[4], al[4];
      ah[0]=Ah[r0*36+k+tg]; ah[1]=Ah[r1*36+k+tg];
      ah[2]=Ah[r0*36+k+tg+4]; ah[3]=Ah[r1*36+k+tg+4];
      al[0]=Al[r0*36+k+tg]; al[1]=Al[r1*36+k+tg];
      al[2]=Al[r0*36+k+tg+4]; al[3]=Al[r1*36+k+tg+4];
      #pragma unroll
      for (int nn=0; nn<4; nn++){
        int col = wn*32 + 8*nn + g;
        unsigned bh0=Bh[col*36+k+tg], bh1=Bh[col*36+k+tg+4];
        unsigned bl0=Bl[col*36+k+tg], bl1=Bl[col*36+k+tg+4];
        mma_tf32(acc[nn], ah, bh0, bh1);
        mma_tf32(acc[nn], al, bh0, bh1);
        mma_tf32(acc[nn], ah, bl0, bl1);
      }
    }
  }
}

// ---------------------------------------------------------------------------
// All four projections (blockIdx.z selects q/k/v/g).
// q/k/v stored pre-converted to tf32; k transposed to [H*D][N].
// ---------------------------------------------------------------------------
__device__ __forceinline__ void proj_store(int proj, int row, int col, float val,
                                           const float* __restrict__ bq){
  if (proj==0){
    val = (val + bq[col]) * (0.2041241452f * L2E);   // D^-0.5 * log2e
    g_q[(col/DD)*NN*DD + row*DD + (col%DD)] = cvt_tf32(val);
  } else if (proj==1){
    g_kT[(size_t)col*NN + row] = cvt_tf32(val);      // [H*D][N]
  } else if (proj==2){
    g_v[(col/DD)*NN*DD + row*DD + (col%DD)] = cvt_tf32(val);
  } else {
    g_gate[row*CC+col] = 1.f/(1.f+__expf(-val));
  }
}

__global__ __launch_bounds__(256) void proj_kernel(const float* __restrict__ bq) {
  extern __shared__ unsigned smu[];
  int proj = blockIdx.z;
  int c0 = blockIdx.x*64, n0 = blockIdx.y*64;
  float acc[4][4] = {};
  gemm_tc(g_xnh, g_xnl, g_wh + proj*WSZ, g_wl + proj*WSZ, n0, c0, acc, smu);
  int lane = threadIdx.x&31, w = threadIdx.x>>5;
  int wm = w>>1, wn = w&1;
  int g = lane>>2, tg = lane&3;
  int row0 = n0 + wm*16 + g, row1 = row0 + 8;
  #pragma unroll
  for (int nn=0;nn<4;nn++){
    int col = c0 + wn*32 + 8*nn + 2*tg;
    proj_store(proj, row0, col,   acc[nn][0], bq);
    proj_store(proj, row0, col+1, acc[nn][1], bq);
    proj_store(proj, row1, col,   acc[nn][2], bq);
    proj_store(proj, row1, col+1, acc[nn][3], bq);
  }
}

// ---------------------------------------------------------------------------
// Tensor-core flash attention, 32-key tiles, cp.async double-buffered.
// Dynamic smem (32256B), float words:
//   sPair[2][64*36] @0     (pair tile; overwritten in place by P)
//   sK  [2][24*40]  @4608  (K^T tf32, stride 40 -> B-frag banks 8tg+g, CF)
//   sV  [2][32*24]  @6528  (V tf32, banks 24tg+g, CF)
// Staging slots fixed per thread; sources advance by constant stride per tile.
// ---------------------------------------------------------------------------
__global__ __launch_bounds__(128) void attn_kernel(const float* __restrict__ pair) {
  extern __shared__ float sm[];
  float* sPair   = sm;                       // 2 x 2304
  unsigned* sK   = (unsigned*)(sm + 4608);   // 2 x 960
  unsigned* sV   = (unsigned*)(sm + 6528);   // 2 x 768

  int h = blockIdx.y, q0 = blockIdx.x*64;
  int tid = threadIdx.x;
  int w = tid>>5, lane = tid&31;
  int g = lane>>2, tg = lane&3;
  int r0 = 16*w + g, r1 = r0 + 8;

  const float* pb     = pair + (size_t)h*NN*NN + (size_t)q0*NN;
  const unsigned* kTb = g_kT + (size_t)h*DD*NN;
  const unsigned* vb  = g_v  + (size_t)h*NN*DD;

  // ---- fixed staging slots (computed once) ----
  const float*    psrc[4]; int pdst[4];
  #pragma unroll
  for (int i=0;i<4;i++){
    int f = tid + 128*i;                   // 512 chunks: 64 rows x 8
    int r = f>>3, c4 = (f&7)*4;
    psrc[i] = pb + (size_t)r*NN + c4;
    pdst[i] = r*36 + c4;
  }
  const unsigned* ksrc[2]; int kdst[2];
  {
    int f = tid;                           // 192 chunks: 24 rows x 8
    ksrc[0] = kTb + (size_t)(f>>3)*NN + (f&7)*4; kdst[0] = (f>>3)*40 + (f&7)*4;
    int f2 = tid + 128;
    ksrc[1] = kTb + (size_t)(f2>>3)*NN + (f2&7)*4; kdst[1] = (f2>>3)*40 + (f2&7)*4;
  }
  const unsigned* vsrc[2]; int vdst[2];
  {
    int f = tid;                           // 192 chunks: 32 rows x 6
    int r = f/6, c = (f-6*r)*4;
    vsrc[0] = vb + r*DD + c; vdst[0] = r*24 + c;
    int f2 = tid + 128; int r2 = f2/6, c2 = (f2-6*r2)*4;
    vsrc[1] = vb + r2*DD + c2; vdst[1] = r2*24 + c2;
  }
  bool lo64 = (tid < 64);

  auto stage = [&](int t, int b){
    int koff = t*32;                       // key offset (elements)
    #pragma unroll
    for (int i=0;i<4;i++) cp16(sPair + b*2304 + pdst[i], psrc[i] + koff);
    cp16(sK + b*960 + kdst[0], ksrc[0] + koff);
    if (lo64) cp16(sK + b*960 + kdst[1], ksrc[1] + koff);
    cp16(sV + b*768 + vdst[0], vsrc[0] + koff*DD);
    if (lo64) cp16(sV + b*768 + vdst[1], vsrc[1] + koff*DD);
    cp_commit();
  };

  // Q A-frags in registers (pre-converted tf32)
  unsigned qa[3][4];
  {
    const unsigned* qb = &g_q[(size_t)h*NN*DD + (size_t)q0*DD];
    #pragma unroll
    for (int j=0;j<3;j++){
      qa[j][0] = qb[r0*DD + 8*j+tg];
      qa[j][1] = qb[r1*DD + 8*j+tg];
      qa[j][2] = qb[r0*DD + 8*j+tg+4];
      qa[j][3] = qb[r1*DD + 8*j+tg+4];
    }
  }
  float m0=-1e30f, m1=-1e30f, l0=0.f, l1=0.f;
  float o[3][4] = {};

  stage(0, 0);
  for (int t=0;t<64;t++){
    int b = t&1, k0 = t*32;
    cp_wait0();
    __syncthreads();
    if (t < 63) stage(t+1, b^1);

    float* bP = sPair + b*2304;
    const unsigned* bK = sK + b*960;
    const unsigned* bV = sV + b*768;
    const float* bb = &g_biask[k0];

    // C := pair*log2e + bias (fp32 exact); bias via L1-cached gmem loads
    float c[4][4];
    #pragma unroll
    for (int nn=0;nn<4;nn++){
      float2 x0 = *(const float2*)&bP[r0*36 + 8*nn+2*tg];
      float2 x1 = *(const float2*)&bP[r1*36 + 8*nn+2*tg];
      float2 bv = *(const float2*)&bb[8*nn+2*tg];
      c[nn][0] = fmaf(x0.x, L2E, bv.x);
      c[nn][1] = fmaf(x0.y, L2E, bv.y);
      c[nn][2] = fmaf(x1.x, L2E, bv.x);
      c[nn][3] = fmaf(x1.y, L2E, bv.y);
    }
    // S += Q.K^T  (B-frags raw, pre-converted)
    #pragma unroll
    for (int j=0;j<3;j++){
      #pragma unroll
      for (int nn=0;nn<4;nn++){
        unsigned b0 = bK[(8*j+tg  )*40 + 8*nn+g];
        unsigned b1 = bK[(8*j+tg+4)*40 + 8*nn+g];
        mma_tf32(c[nn], qa[j], b0, b1);
      }
    }

    // online softmax (log2 domain); P stored pre-converted to tf32
    float rm0=-1e30f, rm1=-1e30f;
    #pragma unroll
    for (int nn=0;nn<4;nn++){
      rm0 = fmaxf(rm0, fmaxf(c[nn][0], c[nn][1]));
      rm1 = fmaxf(rm1, fmaxf(c[nn][2], c[nn][3]));
    }
    rm0 = fmaxf(rm0, __shfl_xor_sync(~0u,rm0,1));
    rm0 = fmaxf(rm0, __shfl_xor_sync(~0u,rm0,2));
    rm1 = fmaxf(rm1, __shfl_xor_sync(~0u,rm1,1));
    rm1 = fmaxf(rm1, __shfl_xor_sync(~0u,rm1,2));
    float mn0 = fmaxf(m0, rm0), mn1 = fmaxf(m1, rm1);
    float a0 = exp2f(m0-mn0), a1 = exp2f(m1-mn1);
    float ls0=0.f, ls1=0.f;
    #pragma unroll
    for (int nn=0;nn<4;nn++){
      float p00 = exp2f(c[nn][0]-mn0);
      float p01 = exp2f(c[nn][1]-mn0);
      float p10 = exp2f(c[nn][2]-mn1);
      float p11 = exp2f(c[nn][3]-mn1);
      ls0 += p00+p01; ls1 += p10+p11;
      *(float2*)&bP[r0*36 + 8*nn+2*tg] =
        make_float2(__uint_as_float(cvt_tf32(p00)), __uint_as_float(cvt_tf32(p01)));
      *(float2*)&bP[r1*36 + 8*nn+2*tg] =
        make_float2(__uint_as_float(cvt_tf32(p10)), __uint_as_float(cvt_tf32(p11)));
    }
    ls0 += __shfl_xor_sync(~0u,ls0,1); ls0 += __shfl_xor_sync(~0u,ls0,2);
    ls1 += __shfl_xor_sync(~0u,ls1,1); ls1 += __shfl_xor_sync(~0u,ls1,2);
    l0 = l0*a0 + ls0; l1 = l1*a1 + ls1; m0 = mn0; m1 = mn1;
    #pragma unroll
    for (int nn=0;nn<3;nn++){
      o[nn][0]*=a0; o[nn][1]*=a0; o[nn][2]*=a1; o[nn][3]*=a1;
    }
    __syncwarp();   // P rows warp-private; order STS before LDS

    // O += P.V  (all frags raw tf32)
    const unsigned* bPu = (const unsigned*)bP;
    #pragma unroll
    for (int j=0;j<4;j++){
      unsigned a[4];
      a[0] = bPu[r0*36 + 8*j+tg];
      a[1] = bPu[r1*36 + 8*j+tg];
      a[2] = bPu[r0*36 + 8*j+tg+4];
      a[3] = bPu[r1*36 + 8*j+tg+4];
      #pragma unroll
      for (int nn=0;nn<3;nn++){
        unsigned b0 = bV[(8*j+tg  )*24 + 8*nn+g];
        unsigned b1 = bV[(8*j+tg+4)*24 + 8*nn+g];
        mma_tf32(o[nn], a, b0, b1);
      }
    }
  }

  // epilogue: normalize + gate -> hi/lo for the output GEMM
  float il0 = 1.f/l0, il1 = 1.f/l1;
  int n0g = q0 + r0, n1g = q0 + r1;
  #pragma unroll
  for (int nn=0;nn<3;nn++){
    int col = h*DD + 8*nn + 2*tg;
    float2 gt0 = *(const float2*)&g_gate[n0g*CC + col];
    float2 gt1 = *(const float2*)&g_gate[n1g*CC + col];
    float y[4] = { o[nn][0]*il0*gt0.x, o[nn][1]*il0*gt0.y,
                   o[nn][2]*il1*gt1.x, o[nn][3]*il1*gt1.y };
    int idx[4] = { n0g*CC+col, n0g*CC+col+1, n1g*CC+col, n1g*CC+col+1 };
    #pragma unroll
    for (int i=0;i<4;i++){
      unsigned hx = cvt_tf32(y[i]);
      g_gatedh[idx[i]] = hx;
      g_gatedl[idx[i]] = cvt_tf32(y[i] - __uint_as_float(hx));
    }
  }
}

// ---------------------------------------------------------------------------
// Output projection: out = gated @ wo.T  (3xTF32, pipelined)
// ---------------------------------------------------------------------------
__global__ __launch_bounds__(256) void out_kernel(float* __restrict__ out) {
  extern __shared__ unsigned smu[];
  int c0 = blockIdx.x*64, n0 = blockIdx.y*64;
  float acc[4][4] = {};
  gemm_tc(g_gatedh, g_gatedl, g_wh + 4*WSZ, g_wl + 4*WSZ, n0, c0, acc, smu);
  int lane = threadIdx.x&31, w = threadIdx.x>>5;
  int wm = w>>1, wn = w&1;
  int g = lane>>2, tg = lane&3;
  int row0 = n0 + wm*16 + g, row1 = row0 + 8;
  #pragma unroll
  for (int nn=0;nn<4;nn++){
    int col = c0 + wn*32 + 8*nn + 2*tg;
    *(float2*)&out[row0*CC+col] = make_float2(acc[nn][0], acc[nn][1]);
    *(float2*)&out[row1*CC+col] = make_float2(acc[nn][2], acc[nn][3]);
  }
}

// ---------------------------------------------------------------------------
extern "C" void kernel_launch(void* const* d_in, const int* in_sizes, int n_in,
                              void* d_out, int out_size) {
  const float* x    = (const float*)d_in[0];
  const float* mask = (const float*)d_in[1];
  const float* pair = (const float*)d_in[2];
  const float* ln_w = (const float*)d_in[3];
  const float* ln_b = (const float*)d_in[4];
  const float* wq   = (const float*)d_in[5];
  const float* bq   = (const float*)d_in[6];
  const float* wk   = (const float*)d_in[7];
  const float* wv   = (const float*)d_in[8];
  const float* wg   = (const float*)d_in[9];
  const float* wo   = (const float*)d_in[10];
  float* out = (float*)d_out;

  cudaFuncSetAttribute(proj_kernel, cudaFuncAttributeMaxDynamicSharedMemorySize, 73728);
  cudaFuncSetAttribute(out_kernel,  cudaFuncAttributeMaxDynamicSharedMemorySize, 73728);
  cudaFuncSetAttribute(attn_kernel, cudaFuncAttributeMaxDynamicSharedMemorySize, 32256);

  ln_kernel<<<NN,128>>>(x,mask,ln_w,ln_b);
  wconv_kernel<<<dim3(WSZ/256,5),256>>>(wq,wk,wv,wg,wo);
  proj_kernel<<<dim3(6,32,4),256,73728>>>(bq);
  attn_kernel<<<dim3(32,16),128,32256>>>(pair);
  out_kernel<<<dim3(6,32),256,73728>>>(out);
}